// round 9
// baseline (speedup 1.0000x reference)
#include <cuda_runtime.h>
#include <cstdint>

#define T_LEN   16777216
#define BLOCK   512
#define ITEMS   16
#define TILE    (BLOCK * ITEMS)          // 8192
#define NTILES  (T_LEN / TILE)           // 2048  (= 1<<11)
#define NT_LOG2 11
#define NWARP   (BLOCK / 32)             // 16
#define FULLMASK 0xffffffffu

// Decoupled-lookback state. NEVER reset: flags are generation-encoded
// (partial = 3*gen+1, inclusive = 3*gen+2; monotonically increasing), and
// g_ctr tickets monotonically increase across launches: gen = ticket >> 11.
__device__ unsigned int g_ctr;                     // zero-initialized once
__device__ unsigned int g_flag[NTILES];            // 0 initially => stale for gen 0
__device__ float g_pA[NTILES], g_pB[NTILES];
__device__ float g_iA[NTILES], g_iB[NTILES];

__global__ __launch_bounds__(BLOCK) void ses_scan(
    const float* __restrict__ y, const float* __restrict__ alpha_p,
    float* __restrict__ out)
{
    // Padded transpose buffer: float4 slot = Q + (Q>>3) for quad index Q.
    // Conflict-free for both striped (consecutive Q) and blocked (Q=4t+i) access.
    __shared__ float sbuf[TILE + TILE / 8];        // 9216 floats = 36 KB
    __shared__ float sh_wB[NWARP];
    __shared__ float sh_carry;
    __shared__ unsigned sh_ticket;

    const int tid  = threadIdx.x;
    const int lane = tid & 31;
    const int wid  = tid >> 5;

    // Dynamic tile ids, increasing within a launch -> lookback never deadlocks.
    if (tid == 0) sh_ticket = atomicAdd(&g_ctr, 1u);
    __syncthreads();
    const unsigned ticket = sh_ticket;
    const int tile = (int)(ticket & (NTILES - 1u));
    const unsigned base3 = 3u * (ticket >> NT_LOG2);   // this launch's flag base

    const float alpha = __ldg(alpha_p);
    const float a = 1.0f - alpha;

    float4* s4 = reinterpret_cast<float4*>(sbuf);

    // ---- phase 1: striped cp.async GMEM -> padded SMEM (4 quads/thread) ----
    {
        const float4* yin = reinterpret_cast<const float4*>(y) + (size_t)tile * (TILE / 4);
        #pragma unroll
        for (int j = 0; j < 4; j++) {
            const int Q = j * BLOCK + tid;
            unsigned saddr = (unsigned)__cvta_generic_to_shared(&s4[Q + (Q >> 3)]);
            asm volatile("cp.async.cg.shared.global [%0], [%1], 16;\n"
                         :: "r"(saddr), "l"(yin + Q) : "memory");
        }
        asm volatile("cp.async.commit_group;\n" ::: "memory");
        asm volatile("cp.async.wait_group 0;\n" ::: "memory");
    }
    __syncthreads();

    // ---- phase 2: blocked read + thread-local serial scan (zero carry-in) ----
    float v[ITEMS];
    #pragma unroll
    for (int i = 0; i < 4; i++) {
        const int Q = 4 * tid + i;
        float4 q = s4[Q + (Q >> 3)];
        v[4*i+0] = q.x; v[4*i+1] = q.y; v[4*i+2] = q.z; v[4*i+3] = q.w;
    }

    // element t: (a, alpha*y_t); global t=0 pinned to (0, y_0)
    float B;
    {
        float p = 0.f;
        const bool first = (tile == 0 && tid == 0);
        #pragma unroll
        for (int i = 0; i < ITEMS; i++) {
            float aa = a, bb = alpha * v[i];
            if (first && i == 0) { aa = 0.f; bb = v[0]; }
            p = fmaf(aa, p, bb);
            v[i] = p;
        }
        B = p;
    }

    // constant-multiplier powers
    float a2 = a*a, a4 = a2*a2, a8 = a4*a4, a16 = a8*a8;

    // ---- warp inclusive scan of B; window-A closed form a^(16d) ----
    float m = a16;
    #pragma unroll
    for (int d = 1; d < 32; d <<= 1) {
        float pB = __shfl_up_sync(FULLMASK, B, d);
        if (lane >= d) B = fmaf(m, pB, B);
        m = m * m;
    }
    const float A512 = m;                      // a^512 = per-warp A
    float exB = __shfl_up_sync(FULLMASK, B, 1);
    if (lane == 0) exB = 0.f;
    if (lane == 31) sh_wB[wid] = B;
    __syncthreads();

    // cross-warp B prefix over warps 0..wid-1 (identity start)
    float WB = 0.f;
    for (int w = 0; w < wid; w++) WB = fmaf(A512, WB, sh_wB[w]);

    // exA = a^(16*lane) (5-bit binary exp on a^16)
    float exA = 1.f;
    { float bp = a16; int e = lane;
      #pragma unroll
      for (int k = 0; k < 5; k++) { if (e & 1) exA *= bp; bp *= bp; e >>= 1; } }
    const float TexB = fmaf(exA, WB, exB);
    // TexA = a^(16*tid) = exA * A512^wid (multiplies only the carry; tile-0 carry = 0)
    float TexA = exA;
    { float wp = A512; int e = wid;
      #pragma unroll
      for (int k = 0; k < 4; k++) { if (e & 1) TexA *= wp; wp *= wp; e >>= 1; } }

    // ---- publish tile aggregate (gen-encoded flag) ----
    float aggA = 0.f, aggB = 0.f;              // live in tid-0 registers
    if (tid == 0) {
        float gB = 0.f;
        #pragma unroll
        for (int w = 0; w < NWARP; w++) gB = fmaf(A512, gB, sh_wB[w]);
        float A8192 = A512 * A512; A8192 *= A8192; A8192 *= A8192; A8192 *= A8192;
        aggA = (tile == 0) ? 0.f : A8192;      // tile 0 truly has A = 0
        aggB = gB;
        if (tile == 0) {
            __stcg(&g_iA[0], 0.f);
            __stcg(&g_iB[0], gB);
            __threadfence();
            atomicExch(&g_flag[0], base3 + 2u);    // inclusive
            sh_carry = 0.f;
        } else {
            __stcg(&g_pA[tile], A8192);
            __stcg(&g_pB[tile], gB);
            __threadfence();
            atomicExch(&g_flag[tile], base3 + 1u); // partial
        }
    }

    // ---- warp-parallel decoupled lookback (warp 0), early-exit on accA==0 ----
    if (wid == 0 && tile > 0) {
        __syncwarp();
        float accA = 1.f, accB = 0.f;
        int pred = tile - 1;
        for (;;) {
            const int idx = pred - lane;       // lane 0 = latest predecessor
            unsigned st;
            if (idx >= 0) {
                unsigned f = *((volatile unsigned*)&g_flag[idx]);
                while (f < base3 + 1u) {       // stale (older gen) or unset
                    __nanosleep(32);
                    f = *((volatile unsigned*)&g_flag[idx]);
                }
                st = f - base3;                // 1=partial 2=inclusive
            } else st = 2u;
            __threadfence();
            float mA, mB;
            if (idx < 0)      { mA = 1.f;                mB = 0.f; }
            else if (st == 2u){ mA = __ldcg(&g_iA[idx]); mB = __ldcg(&g_iB[idx]); }
            else              { mA = __ldcg(&g_pA[idx]); mB = __ldcg(&g_pB[idx]); }

            const unsigned bal = __ballot_sync(FULLMASK, st == 2u);
            const int mm = bal ? (__ffs(bal) - 1) : 32;
            const int start = (mm < 32) ? mm : 31;

            // window combine earliest->latest: c = combine(c, s_L)
            float cA = 1.f, cB = 0.f;
            for (int L = start; L >= 0; --L) {
                float sA = __shfl_sync(FULLMASK, mA, L);
                float sB = __shfl_sync(FULLMASK, mB, L);
                cB = fmaf(sA, cB, sB);
                cA = cA * sA;
            }
            float nB = fmaf(accA, cB, accB);
            accA = cA * accA;
            accB = nB;

            // accA == 0 -> result exactly independent of earlier tiles
            if (mm < 32 || accA == 0.0f) break;
            pred -= 32;
        }
        if (lane == 0) {
            __stcg(&g_iA[tile], accA * aggA);
            __stcg(&g_iB[tile], fmaf(aggA, accB, aggB));
            __threadfence();
            atomicExch(&g_flag[tile], base3 + 2u);
            sh_carry = accB;                   // level just before this tile
        }
    }
    __syncthreads();

    // ---- fixup ----
    const float c = fmaf(TexA, sh_carry, TexB);
    {
        float cp = c * a;
        #pragma unroll
        for (int i = 0; i < ITEMS; i++) { v[i] += cp; cp *= a; }
    }

    // ---- phase 3: blocked -> SMEM, striped streaming stores ----
    #pragma unroll
    for (int i = 0; i < 4; i++) {
        const int Q = 4 * tid + i;
        s4[Q + (Q >> 3)] = make_float4(v[4*i+0], v[4*i+1], v[4*i+2], v[4*i+3]);
    }
    __syncthreads();

    {
        float4* o4 = reinterpret_cast<float4*>(out) + (size_t)tile * (TILE / 4);
        if (tile != NTILES - 1) {
            #pragma unroll
            for (int j = 0; j < 4; j++) {
                const int Q = j * BLOCK + tid;
                __stcs(&o4[Q], s4[Q + (Q >> 3)]);
            }
        } else {
            // last tile: output length T_LEN-1, never write index T_LEN-1
            const long long tbase = (long long)tile * TILE;
            #pragma unroll
            for (int j = 0; j < 4; j++) {
                const int Q = j * BLOCK + tid;
                float4 q = s4[Q + (Q >> 3)];
                const long long g = tbase + 4LL * Q;
                if (g + 4 <= (long long)(T_LEN - 1)) {
                    __stcs(&o4[Q], q);
                } else {
                    float* op = out + g;
                    if (g + 0 < (long long)(T_LEN - 1)) op[0] = q.x;
                    if (g + 1 < (long long)(T_LEN - 1)) op[1] = q.y;
                    if (g + 2 < (long long)(T_LEN - 1)) op[2] = q.z;
                    if (g + 3 < (long long)(T_LEN - 1)) op[3] = q.w;
                }
            }
        }
    }
}

extern "C" void kernel_launch(void* const* d_in, const int* in_sizes, int n_in,
                              void* d_out, int out_size) {
    const float* y     = (const float*)d_in[0];   // timeseries, T_LEN fp32
    const float* alpha = (const float*)d_in[1];   // 1 fp32
    float* out = (float*)d_out;                   // T_LEN-1 fp32
    (void)in_sizes; (void)n_in; (void)out_size;

    ses_scan<<<NTILES, BLOCK>>>(y, alpha, out);   // single launch, no init pass
}